// round 1
// baseline (speedup 1.0000x reference)
#include <cuda_runtime.h>
#include <cstddef>

// GRU_AE: 4-layer stacked GRU (32->30->15->30->16) + FC(16->10), B=512, T=2048.
// Fully fused persistent kernel: one warp advances one batch element through all
// 4 layers + FC per timestep. Hidden state is lane-distributed (H<=32) and shared
// via __shfl_sync (warp-synchronous, no barriers in the time loop). Weights are
// staged once into shared memory, zero-padded to multiples of 4 for LDS.128.

#define T_LEN 2048
#define B_SZ  512
#define I_DIM 32
#define FULLM 0xffffffffu

// ---- shared-memory layout (floats) ----
#define OFF_WIH1 0              // 90 x 32
#define OFF_WHH1 2880           // 90 x 32 (30 padded to 32)
#define OFF_WIH2 5760           // 45 x 32 (30 -> 32)
#define OFF_WHH2 7200           // 45 x 16 (15 -> 16)
#define OFF_WIH3 7920           // 90 x 16 (15 -> 16)
#define OFF_WHH3 9360           // 90 x 32 (30 -> 32)
#define OFF_WIH4 12240          // 48 x 32 (30 -> 32)
#define OFF_WHH4 13776          // 48 x 16
#define OFF_FCW  14544          // 10 x 16
#define SMEM_FLOATS 14704
#define SMEM_BYTES (SMEM_FLOATS * 4)

static __device__ __forceinline__ float sigm(float x) {
    return __fdividef(1.0f, 1.0f + __expf(-x));
}
static __device__ __forceinline__ float tanh_f(float x) {
    // tanh(x) = 1 - 2/(e^{2x}+1); saturates correctly via expf -> 0 / inf
    float e = __expf(2.0f * x);
    return 1.0f - __fdividef(2.0f, e + 1.0f);
}

// Accumulate 3 gate dot-products over a lane-distributed vector hv.
// NQ = padded_width/4. Rows w0,w1,w2 are zero-padded so out-of-range lanes
// (which hold hv == 0 or are multiplied by 0-weights) contribute nothing.
template <int NQ>
static __device__ __forceinline__ void dot3(const float* w0, const float* w1,
                                            const float* w2, float hv,
                                            float& a0, float& a1, float& a2) {
    const float4* p0 = (const float4*)w0;
    const float4* p1 = (const float4*)w1;
    const float4* p2 = (const float4*)w2;
#pragma unroll
    for (int q = 0; q < NQ; ++q) {
        float4 A = p0[q], B = p1[q], C = p2[q];
#pragma unroll
        for (int k = 0; k < 4; ++k) {
            float v = __shfl_sync(FULLM, hv, q * 4 + k);
            a0 = fmaf(((const float*)&A)[k], v, a0);
            a1 = fmaf(((const float*)&B)[k], v, a1);
            a2 = fmaf(((const float*)&C)[k], v, a2);
        }
    }
}

// Cooperative copy with row padding (pad columns zeroed).
static __device__ __forceinline__ void load_pad(float* dst, const float* src,
                                                int rows, int w, int wp,
                                                int tid, int nt) {
    for (int idx = tid; idx < rows * wp; idx += nt) {
        int r = idx / wp;
        int c = idx - r * wp;
        dst[idx] = (c < w) ? src[r * w + c] : 0.0f;
    }
}

__global__ void __launch_bounds__(128, 1)
gru_ae_fused_kernel(const float* __restrict__ x,
                    const float* __restrict__ fc_w,  const float* __restrict__ fc_b,
                    const float* __restrict__ wih1,  const float* __restrict__ whh1,
                    const float* __restrict__ bih1,  const float* __restrict__ bhh1,
                    const float* __restrict__ wih2,  const float* __restrict__ whh2,
                    const float* __restrict__ bih2,  const float* __restrict__ bhh2,
                    const float* __restrict__ wih3,  const float* __restrict__ whh3,
                    const float* __restrict__ bih3,  const float* __restrict__ bhh3,
                    const float* __restrict__ wih4,  const float* __restrict__ whh4,
                    const float* __restrict__ bih4,  const float* __restrict__ bhh4,
                    float* __restrict__ out) {
    extern __shared__ float sm[];
    const int tid = threadIdx.x;
    const int nt  = blockDim.x;

    load_pad(sm + OFF_WIH1, wih1, 90, 32, 32, tid, nt);
    load_pad(sm + OFF_WHH1, whh1, 90, 30, 32, tid, nt);
    load_pad(sm + OFF_WIH2, wih2, 45, 30, 32, tid, nt);
    load_pad(sm + OFF_WHH2, whh2, 45, 15, 16, tid, nt);
    load_pad(sm + OFF_WIH3, wih3, 90, 15, 16, tid, nt);
    load_pad(sm + OFF_WHH3, whh3, 90, 30, 32, tid, nt);
    load_pad(sm + OFF_WIH4, wih4, 48, 30, 32, tid, nt);
    load_pad(sm + OFF_WHH4, whh4, 48, 16, 16, tid, nt);
    load_pad(sm + OFF_FCW,  fc_w, 10, 16, 16, tid, nt);
    __syncthreads();

    const int warp = tid >> 5;
    const int lane = tid & 31;
    const int b = blockIdx.x * 4 + warp;   // grid = 128 blocks -> b in [0,512)

    // Clamped per-lane row indices (inactive lanes alias row 0; results unused).
    const int i30 = (lane < 30) ? lane : 0;
    const int i15 = (lane < 15) ? lane : 0;
    const int i16 = (lane < 16) ? lane : 0;
    const int i10 = (lane < 10) ? lane : 0;

    // Per-lane weight-row pointers (shared memory).
    const float* w1r = sm + OFF_WIH1 + i30 * 32;
    const float* w1z = sm + OFF_WIH1 + (30 + i30) * 32;
    const float* w1n = sm + OFF_WIH1 + (60 + i30) * 32;
    const float* u1r = sm + OFF_WHH1 + i30 * 32;
    const float* u1z = sm + OFF_WHH1 + (30 + i30) * 32;
    const float* u1n = sm + OFF_WHH1 + (60 + i30) * 32;

    const float* w2r = sm + OFF_WIH2 + i15 * 32;
    const float* w2z = sm + OFF_WIH2 + (15 + i15) * 32;
    const float* w2n = sm + OFF_WIH2 + (30 + i15) * 32;
    const float* u2r = sm + OFF_WHH2 + i15 * 16;
    const float* u2z = sm + OFF_WHH2 + (15 + i15) * 16;
    const float* u2n = sm + OFF_WHH2 + (30 + i15) * 16;

    const float* w3r = sm + OFF_WIH3 + i30 * 16;
    const float* w3z = sm + OFF_WIH3 + (30 + i30) * 16;
    const float* w3n = sm + OFF_WIH3 + (60 + i30) * 16;
    const float* u3r = sm + OFF_WHH3 + i30 * 32;
    const float* u3z = sm + OFF_WHH3 + (30 + i30) * 32;
    const float* u3n = sm + OFF_WHH3 + (60 + i30) * 32;

    const float* w4r = sm + OFF_WIH4 + i16 * 32;
    const float* w4z = sm + OFF_WIH4 + (16 + i16) * 32;
    const float* w4n = sm + OFF_WIH4 + (32 + i16) * 32;
    const float* u4r = sm + OFF_WHH4 + i16 * 16;
    const float* u4z = sm + OFF_WHH4 + (16 + i16) * 16;
    const float* u4n = sm + OFF_WHH4 + (32 + i16) * 16;

    const float* wfc = sm + OFF_FCW + i10 * 16;

    // Biases into registers. r/z gates: b_ih + b_hh fold; n gate keeps them
    // separate (b_hh_n sits inside the r* term).
    const float b1r = bih1[i30] + bhh1[i30];
    const float b1z = bih1[30 + i30] + bhh1[30 + i30];
    const float b1nx = bih1[60 + i30], b1nh = bhh1[60 + i30];

    const float b2r = bih2[i15] + bhh2[i15];
    const float b2z = bih2[15 + i15] + bhh2[15 + i15];
    const float b2nx = bih2[30 + i15], b2nh = bhh2[30 + i15];

    const float b3r = bih3[i30] + bhh3[i30];
    const float b3z = bih3[30 + i30] + bhh3[30 + i30];
    const float b3nx = bih3[60 + i30], b3nh = bhh3[60 + i30];

    const float b4r = bih4[i16] + bhh4[i16];
    const float b4z = bih4[16 + i16] + bhh4[16 + i16];
    const float b4nx = bih4[32 + i16], b4nh = bhh4[32 + i16];

    const float bfc = fc_b[i10];

    float h1 = 0.0f, h2 = 0.0f, h3 = 0.0f, h4 = 0.0f;

    const float* xrow = x + (size_t)b * T_LEN * I_DIM;
    float* orow = out + (size_t)b * 10 * T_LEN + (size_t)i10 * T_LEN;

    float xv = xrow[lane];  // x[b][0][lane]

    for (int t = 0; t < T_LEN; ++t) {
        // Prefetch next timestep's input (hidden under ~1k cycles of compute).
        float xnext = 0.0f;
        if (t + 1 < T_LEN) xnext = xrow[(size_t)(t + 1) * I_DIM + lane];

        // ---------- layer 1: in=x (32), hid=h1 (30) ----------
        {
            float axr = 0.f, axz = 0.f, axn = 0.f;
            dot3<8>(w1r, w1z, w1n, xv, axr, axz, axn);
            float ahr = 0.f, ahz = 0.f, ahn = 0.f;
            dot3<8>(u1r, u1z, u1n, h1, ahr, ahz, ahn);
            float r = sigm(axr + ahr + b1r);
            float z = sigm(axz + ahz + b1z);
            float n = tanh_f(axn + b1nx + r * (ahn + b1nh));
            float hn = n + z * (h1 - n);
            if (lane < 30) h1 = hn;   // lanes 30,31 stay 0 (safe shfl source)
        }
        // ---------- layer 2: in=h1 (30), hid=h2 (15) ----------
        {
            float axr = 0.f, axz = 0.f, axn = 0.f;
            dot3<8>(w2r, w2z, w2n, h1, axr, axz, axn);
            float ahr = 0.f, ahz = 0.f, ahn = 0.f;
            dot3<4>(u2r, u2z, u2n, h2, ahr, ahz, ahn);
            float r = sigm(axr + ahr + b2r);
            float z = sigm(axz + ahz + b2z);
            float n = tanh_f(axn + b2nx + r * (ahn + b2nh));
            float hn = n + z * (h2 - n);
            if (lane < 15) h2 = hn;
        }
        // ---------- layer 3: in=h2 (15), hid=h3 (30) ----------
        {
            float axr = 0.f, axz = 0.f, axn = 0.f;
            dot3<4>(w3r, w3z, w3n, h2, axr, axz, axn);
            float ahr = 0.f, ahz = 0.f, ahn = 0.f;
            dot3<8>(u3r, u3z, u3n, h3, ahr, ahz, ahn);
            float r = sigm(axr + ahr + b3r);
            float z = sigm(axz + ahz + b3z);
            float n = tanh_f(axn + b3nx + r * (ahn + b3nh));
            float hn = n + z * (h3 - n);
            if (lane < 30) h3 = hn;
        }
        // ---------- layer 4: in=h3 (30), hid=h4 (16) ----------
        {
            float axr = 0.f, axz = 0.f, axn = 0.f;
            dot3<8>(w4r, w4z, w4n, h3, axr, axz, axn);
            float ahr = 0.f, ahz = 0.f, ahn = 0.f;
            dot3<4>(u4r, u4z, u4n, h4, ahr, ahz, ahn);
            float r = sigm(axr + ahr + b4r);
            float z = sigm(axz + ahz + b4z);
            float n = tanh_f(axn + b4nx + r * (ahn + b4nh));
            float hn = n + z * (h4 - n);
            if (lane < 16) h4 = hn;
        }
        // ---------- FC: h4 (16) -> 10, store out[b][c][t] ----------
        {
            float acc = bfc;
            const float4* pf = (const float4*)wfc;
#pragma unroll
            for (int q = 0; q < 4; ++q) {
                float4 A = pf[q];
#pragma unroll
                for (int k = 0; k < 4; ++k) {
                    float v = __shfl_sync(FULLM, h4, q * 4 + k);
                    acc = fmaf(((const float*)&A)[k], v, acc);
                }
            }
            if (lane < 10) orow[t] = acc;
        }
        xv = xnext;
    }
}

extern "C" void kernel_launch(void* const* d_in, const int* in_sizes, int n_in,
                              void* d_out, int out_size) {
    (void)in_sizes; (void)n_in; (void)out_size;
    const float* x    = (const float*)d_in[0];
    const float* fcw  = (const float*)d_in[1];
    const float* fcb  = (const float*)d_in[2];
    const float* wih1 = (const float*)d_in[3];
    const float* whh1 = (const float*)d_in[4];
    const float* bih1 = (const float*)d_in[5];
    const float* bhh1 = (const float*)d_in[6];
    const float* wih2 = (const float*)d_in[7];
    const float* whh2 = (const float*)d_in[8];
    const float* bih2 = (const float*)d_in[9];
    const float* bhh2 = (const float*)d_in[10];
    const float* wih3 = (const float*)d_in[11];
    const float* whh3 = (const float*)d_in[12];
    const float* bih3 = (const float*)d_in[13];
    const float* bhh3 = (const float*)d_in[14];
    const float* wih4 = (const float*)d_in[15];
    const float* whh4 = (const float*)d_in[16];
    const float* bih4 = (const float*)d_in[17];
    const float* bhh4 = (const float*)d_in[18];
    float* out = (float*)d_out;

    cudaFuncSetAttribute(gru_ae_fused_kernel,
                         cudaFuncAttributeMaxDynamicSharedMemorySize, SMEM_BYTES);

    gru_ae_fused_kernel<<<128, 128, SMEM_BYTES>>>(
        x, fcw, fcb,
        wih1, whh1, bih1, bhh1,
        wih2, whh2, bih2, bhh2,
        wih3, whh3, bih3, bhh3,
        wih4, whh4, bih4, bhh4,
        out);
}

// round 3
// speedup vs baseline: 1.9083x; 1.9083x over previous
#include <cuda_runtime.h>
#include <cstddef>

// GRU_AE fused, warp-specialized + layer-pipelined.
// Block = 4 batch elements, 13 warps:
//   wid 0..11: (layer = wid/3, gate = wid%3 in {r,z,n}) — weight rows in REGISTERS
//   wid 12:    FC + x loader
// Layer L (delay d=L-1) processes timestep s = k-d at iteration k. Vectors move
// between layers via double-buffered smem float4 arrays packed [col][4 batches].
// 2 bar.syncs per iteration (gate-compute/exchange -> combine).

#define T_LEN 2048
#define NTHR  416   // 13 warps
#define NBLK  128   // 128 * 4 = 512 batches

static __device__ __forceinline__ void barrier_all() {
    asm volatile("bar.sync 0, %0;" :: "n"(NTHR) : "memory");
}

static __device__ __forceinline__ float sigm(float x) {
    return __fdividef(1.0f, 1.0f + __expf(-x));
}
static __device__ __forceinline__ float tanh_f(float x) {
    float e = __expf(2.0f * x);
    return 1.0f - __fdividef(2.0f, e + 1.0f);
}

// One gate-warp's role for the whole run.
// IN/HID compile-time so weight arrays stay in registers (fully unrolled).
// IS_N: the n-gate warp keeps its two partial sums across the barrier and
// combines with r,z in phase B, producing h_new.
template <int IN, int HID, bool IS_N>
static __device__ void gate_warp(
    const float* __restrict__ wih_m, const float* __restrict__ whh_m,
    const float* __restrict__ bih,   const float* __restrict__ bhh,
    int gate, int lane, int delay,
    const float4 (*vb)[32],   // [2][32] input vector (prev layer h, or x)
    float4 (*hb)[32],         // [2][32] own hidden state
    float4* gwr,              // write target for r/z gate (phase A)
    const float4* rb_l, const float4* zb_l)  // r,z buffers (N phase B)
{
    const int hc  = (lane < HID) ? lane : 0;
    const int row = gate * HID + hc;

    float wih[IN], whh[HID];
#pragma unroll
    for (int c = 0; c < IN; ++c)  wih[c] = __ldg(wih_m + row * IN + c);
#pragma unroll
    for (int c = 0; c < HID; ++c) whh[c] = __ldg(whh_m + row * HID + c);

    float bA, bB = 0.0f;
    if (IS_N) { bA = __ldg(bih + row); bB = __ldg(bhh + row); }
    else      { bA = __ldg(bih + row) + __ldg(bhh + row); }

    float4 aA = {0, 0, 0, 0}, aB = {0, 0, 0, 0};

    for (int k = 0; k < T_LEN + 4; ++k) {
        const int  s   = k - delay;
        const bool act = (s >= 0) && (s < T_LEN);
        if (act) {
            const int pp = (k + 1) & 1;           // producer parity
            const float4* v = vb[pp];
            const float4* h = hb[pp];
            aA.x = bA; aA.y = bA; aA.z = bA; aA.w = bA;
#pragma unroll
            for (int c = 0; c < IN; ++c) {
                float4 t = v[c];
                aA.x = fmaf(wih[c], t.x, aA.x);
                aA.y = fmaf(wih[c], t.y, aA.y);
                aA.z = fmaf(wih[c], t.z, aA.z);
                aA.w = fmaf(wih[c], t.w, aA.w);
            }
            if (IS_N) {
                aB.x = bB; aB.y = bB; aB.z = bB; aB.w = bB;
#pragma unroll
                for (int c = 0; c < HID; ++c) {
                    float4 t = h[c];
                    aB.x = fmaf(whh[c], t.x, aB.x);
                    aB.y = fmaf(whh[c], t.y, aB.y);
                    aB.z = fmaf(whh[c], t.z, aB.z);
                    aB.w = fmaf(whh[c], t.w, aB.w);
                }
            } else {
#pragma unroll
                for (int c = 0; c < HID; ++c) {
                    float4 t = h[c];
                    aA.x = fmaf(whh[c], t.x, aA.x);
                    aA.y = fmaf(whh[c], t.y, aA.y);
                    aA.z = fmaf(whh[c], t.z, aA.z);
                    aA.w = fmaf(whh[c], t.w, aA.w);
                }
                float4 g;
                g.x = sigm(aA.x); g.y = sigm(aA.y);
                g.z = sigm(aA.z); g.w = sigm(aA.w);
                if (lane < HID) gwr[lane] = g;
            }
        }
        barrier_all();                       // phase A -> phase B
        if (IS_N && act) {
            float4 r  = rb_l[hc];
            float4 z  = zb_l[hc];
            float4 hp = hb[(k + 1) & 1][hc];
            float4 n;
            n.x = tanh_f(fmaf(r.x, aB.x, aA.x));
            n.y = tanh_f(fmaf(r.y, aB.y, aA.y));
            n.z = tanh_f(fmaf(r.z, aB.z, aA.z));
            n.w = tanh_f(fmaf(r.w, aB.w, aA.w));
            float4 hn;
            hn.x = n.x + z.x * (hp.x - n.x);
            hn.y = n.y + z.y * (hp.y - n.y);
            hn.z = n.z + z.z * (hp.z - n.z);
            hn.w = n.w + z.w * (hp.w - n.w);
            if (lane < HID) hb[k & 1][lane] = hn;
        }
        barrier_all();                       // phase B -> next phase A
    }
}

// FC (stagger t = k-4) + x prefetcher (loads x(k+1) in phase A, publishes in B).
static __device__ void fc_warp(
    const float* __restrict__ fcw, const float* __restrict__ fcb,
    const float* __restrict__ x,   float* __restrict__ out,
    int bbase, int lane,
    const float4 (*hb4)[32], float4 (*xb)[32])
{
    const int c10 = (lane < 10) ? lane : 0;
    float w[16];
#pragma unroll
    for (int c = 0; c < 16; ++c) w[c] = __ldg(fcw + c10 * 16 + c);
    const float bfc = __ldg(fcb + c10);

    for (int k = 0; k < T_LEN + 4; ++k) {
        const bool ldx = (k + 1 < T_LEN);
        float xr0 = 0, xr1 = 0, xr2 = 0, xr3 = 0;
        if (ldx) {
            size_t off = (size_t)(k + 1) * 32 + lane;
            xr0 = __ldg(x + (size_t)(bbase + 0) * T_LEN * 32 + off);
            xr1 = __ldg(x + (size_t)(bbase + 1) * T_LEN * 32 + off);
            xr2 = __ldg(x + (size_t)(bbase + 2) * T_LEN * 32 + off);
            xr3 = __ldg(x + (size_t)(bbase + 3) * T_LEN * 32 + off);
        }
        const int t = k - 4;
        if (t >= 0) {
            const float4* h4 = hb4[(k + 1) & 1];
            float4 acc = {bfc, bfc, bfc, bfc};
#pragma unroll
            for (int c = 0; c < 16; ++c) {
                float4 v = h4[c];
                acc.x = fmaf(w[c], v.x, acc.x);
                acc.y = fmaf(w[c], v.y, acc.y);
                acc.z = fmaf(w[c], v.z, acc.z);
                acc.w = fmaf(w[c], v.w, acc.w);
            }
            if (lane < 10) {
                size_t base = ((size_t)bbase * 10 + lane) * T_LEN + t;
                out[base]                         = acc.x;
                out[base + 10 * (size_t)T_LEN]    = acc.y;
                out[base + 20 * (size_t)T_LEN]    = acc.z;
                out[base + 30 * (size_t)T_LEN]    = acc.w;
            }
        }
        barrier_all();
        if (ldx) {
            float4 xv = {xr0, xr1, xr2, xr3};
            xb[k & 1][lane] = xv;
        }
        barrier_all();
    }
}

__global__ void __launch_bounds__(NTHR, 1)
gru_ae_pipe_kernel(const float* __restrict__ x,
                   const float* __restrict__ fcw,  const float* __restrict__ fcb,
                   const float* __restrict__ wih1, const float* __restrict__ whh1,
                   const float* __restrict__ bih1, const float* __restrict__ bhh1,
                   const float* __restrict__ wih2, const float* __restrict__ whh2,
                   const float* __restrict__ bih2, const float* __restrict__ bhh2,
                   const float* __restrict__ wih3, const float* __restrict__ whh3,
                   const float* __restrict__ bih3, const float* __restrict__ bhh3,
                   const float* __restrict__ wih4, const float* __restrict__ whh4,
                   const float* __restrict__ bih4, const float* __restrict__ bhh4,
                   float* __restrict__ out)
{
    __shared__ float4 xb[2][32];
    __shared__ float4 hb1[2][32], hb2[2][32], hb3[2][32], hb4[2][32];
    __shared__ float4 rb[4][32], zb[4][32];

    const int tid  = threadIdx.x;
    const int wid  = tid >> 5;
    const int lane = tid & 31;
    const int bbase = blockIdx.x * 4;

    // Zero all buffers (h(-1)=0; padded lanes stay 0 forever).
    {
        float4 z4 = {0, 0, 0, 0};
        for (int i = tid; i < 64; i += NTHR) {
            (&xb[0][0])[i] = z4; (&hb1[0][0])[i] = z4; (&hb2[0][0])[i] = z4;
            (&hb3[0][0])[i] = z4; (&hb4[0][0])[i] = z4;
        }
        for (int i = tid; i < 128; i += NTHR) {
            (&rb[0][0])[i] = z4; (&zb[0][0])[i] = z4;
        }
    }
    __syncthreads();

    // Preload x(0) into xb[1] (consumed at k=0, parity (0+1)&1 = 1).
    if (wid == 12) {
        float4 xv;
        xv.x = __ldg(x + (size_t)(bbase + 0) * T_LEN * 32 + lane);
        xv.y = __ldg(x + (size_t)(bbase + 1) * T_LEN * 32 + lane);
        xv.z = __ldg(x + (size_t)(bbase + 2) * T_LEN * 32 + lane);
        xv.w = __ldg(x + (size_t)(bbase + 3) * T_LEN * 32 + lane);
        xb[1][lane] = xv;
    }
    __syncthreads();

    // Role dispatch. Every role executes exactly 2*(T_LEN+4) bar.syncs.
    if      (wid == 0)  gate_warp<32, 30, false>(wih1, whh1, bih1, bhh1, 0, lane, 0, xb,  hb1, rb[0], rb[0], zb[0]);
    else if (wid == 1)  gate_warp<32, 30, false>(wih1, whh1, bih1, bhh1, 1, lane, 0, xb,  hb1, zb[0], rb[0], zb[0]);
    else if (wid == 2)  gate_warp<32, 30, true >(wih1, whh1, bih1, bhh1, 2, lane, 0, xb,  hb1, rb[0], rb[0], zb[0]);
    else if (wid == 3)  gate_warp<30, 15, false>(wih2, whh2, bih2, bhh2, 0, lane, 1, hb1, hb2, rb[1], rb[1], zb[1]);
    else if (wid == 4)  gate_warp<30, 15, false>(wih2, whh2, bih2, bhh2, 1, lane, 1, hb1, hb2, zb[1], rb[1], zb[1]);
    else if (wid == 5)  gate_warp<30, 15, true >(wih2, whh2, bih2, bhh2, 2, lane, 1, hb1, hb2, rb[1], rb[1], zb[1]);
    else if (wid == 6)  gate_warp<15, 30, false>(wih3, whh3, bih3, bhh3, 0, lane, 2, hb2, hb3, rb[2], rb[2], zb[2]);
    else if (wid == 7)  gate_warp<15, 30, false>(wih3, whh3, bih3, bhh3, 1, lane, 2, hb2, hb3, zb[2], rb[2], zb[2]);
    else if (wid == 8)  gate_warp<15, 30, true >(wih3, whh3, bih3, bhh3, 2, lane, 2, hb2, hb3, rb[2], rb[2], zb[2]);
    else if (wid == 9)  gate_warp<30, 16, false>(wih4, whh4, bih4, bhh4, 0, lane, 3, hb3, hb4, rb[3], rb[3], zb[3]);
    else if (wid == 10) gate_warp<30, 16, false>(wih4, whh4, bih4, bhh4, 1, lane, 3, hb3, hb4, zb[3], rb[3], zb[3]);
    else if (wid == 11) gate_warp<30, 16, true >(wih4, whh4, bih4, bhh4, 2, lane, 3, hb3, hb4, rb[3], rb[3], zb[3]);
    else                fc_warp(fcw, fcb, x, out, bbase, lane, hb4, xb);
}

extern "C" void kernel_launch(void* const* d_in, const int* in_sizes, int n_in,
                              void* d_out, int out_size) {
    (void)in_sizes; (void)n_in; (void)out_size;
    const float* x    = (const float*)d_in[0];
    const float* fcw  = (const float*)d_in[1];
    const float* fcb  = (const float*)d_in[2];
    const float* wih1 = (const float*)d_in[3];
    const float* whh1 = (const float*)d_in[4];
    const float* bih1 = (const float*)d_in[5];
    const float* bhh1 = (const float*)d_in[6];
    const float* wih2 = (const float*)d_in[7];
    const float* whh2 = (const float*)d_in[8];
    const float* bih2 = (const float*)d_in[9];
    const float* bhh2 = (const float*)d_in[10];
    const float* wih3 = (const float*)d_in[11];
    const float* whh3 = (const float*)d_in[12];
    const float* bih3 = (const float*)d_in[13];
    const float* bhh3 = (const float*)d_in[14];
    const float* wih4 = (const float*)d_in[15];
    const float* whh4 = (const float*)d_in[16];
    const float* bih4 = (const float*)d_in[17];
    const float* bhh4 = (const float*)d_in[18];
    float* out = (float*)d_out;

    gru_ae_pipe_kernel<<<NBLK, NTHR>>>(
        x, fcw, fcb,
        wih1, whh1, bih1, bhh1,
        wih2, whh2, bih2, bhh2,
        wih3, whh3, bih3, bhh3,
        wih4, whh4, bih4, bhh4,
        out);
}

// round 5
// speedup vs baseline: 2.5794x; 1.3517x over previous
#include <cuda_runtime.h>
#include <cstddef>

// GRU_AE fused, warp-specialized + layer-pipelined, single global barrier/step.
// Block = 4 batch elements, 13 warps:
//   wid 0..11: (layer = wid/3, gate = wid%3 in {r,z,n}) — weight rows in REGISTERS
//   wid 12:    FC + x loader (ring-4 prefetch, distance 3)
// Per iteration: all gate warps compute dots (f32x2 packed FFMA); r/z publish
// sigmoid gates then bar.arrive on the layer barrier; the n-warp bar.syncs it,
// combines to h_new, publishes; ONE global bar.sync ends the iteration and
// makes all smem writes visible for the next one.

#define T_LEN 2048
#define NTHR  416   // 13 warps
#define NBLK  128   // 128 * 4 = 512 batches

#define BAR_SYNC(id, cnt)   asm volatile("bar.sync %0, %1;"   :: "n"(id), "n"(cnt) : "memory")
#define BAR_ARRIVE(id, cnt) asm volatile("bar.arrive %0, %1;" :: "n"(id), "n"(cnt) : "memory")

#define PACK2(d, s)       asm("mov.b64 %0, {%1, %1};" : "=l"(d) : "f"(s))
#define UNPACK2(a, b, s)  asm("mov.b64 {%0, %1}, %2;" : "=f"(a), "=f"(b) : "l"(s))
#define FMA2(acc, w, v)   asm("fma.rn.f32x2 %0, %1, %2, %0;" : "+l"(acc) : "l"(w), "l"(v))

static __device__ __forceinline__ float sigm(float x) {
    return __fdividef(1.0f, 1.0f + __expf(-x));
}
static __device__ __forceinline__ float tanh_f(float x) {
    float e = __expf(2.0f * x);
    return 1.0f - __fdividef(2.0f, e + 1.0f);
}

// One gate-warp's role for the whole run. Weights in registers (unrolled).
// XRING: input vector buffer is the 4-deep x ring (layer 1) vs 2-deep h buffer.
template <int IN, int HID, bool IS_N, bool XRING, int BARID>
static __device__ void gate_warp(
    const float* __restrict__ wih_m, const float* __restrict__ whh_m,
    const float* __restrict__ bih,   const float* __restrict__ bhh,
    int gate, int lane, int delay,
    const float4 (*vb)[32],   // input vector buffer (x ring or prev-layer h)
    float4 (*hb)[32],         // [2][32] own hidden double buffer
    float4* gwr,              // r/z gate write target (unused for n)
    const float4* rb_l, const float4* zb_l)  // r,z read (n only)
{
    const int hc  = (lane < HID) ? lane : 0;
    const int row = gate * HID + hc;

    float wih[IN], whh[HID];
#pragma unroll
    for (int c = 0; c < IN; ++c)  wih[c] = __ldg(wih_m + row * IN + c);
#pragma unroll
    for (int c = 0; c < HID; ++c) whh[c] = __ldg(whh_m + row * HID + c);

    unsigned long long bpA, bpB = 0;
    if (IS_N) {
        float bA = __ldg(bih + row), bB = __ldg(bhh + row);
        PACK2(bpA, bA); PACK2(bpB, bB);
    } else {
        float bA = __ldg(bih + row) + __ldg(bhh + row);
        PACK2(bpA, bA);
    }

    for (int k = 0; k < T_LEN + 4; ++k) {
        const int  s   = k - delay;
        const bool act = (s >= 0) && (s < T_LEN);
        unsigned long long a0 = bpA, a1 = bpA, b0 = bpB, b1 = bpB;
        if (act) {
            const float4* v = XRING ? vb[k & 3] : vb[(k + 1) & 1];
            const float4* h = hb[(k + 1) & 1];
#pragma unroll
            for (int c = 0; c < IN; ++c) {
                longlong2 t = *(const longlong2*)(v + c);
                unsigned long long wp; PACK2(wp, wih[c]);
                FMA2(a0, wp, (unsigned long long)t.x);
                FMA2(a1, wp, (unsigned long long)t.y);
            }
#pragma unroll
            for (int c = 0; c < HID; ++c) {
                longlong2 t = *(const longlong2*)(h + c);
                unsigned long long wp; PACK2(wp, whh[c]);
                if (IS_N) {
                    FMA2(b0, wp, (unsigned long long)t.x);
                    FMA2(b1, wp, (unsigned long long)t.y);
                } else {
                    FMA2(a0, wp, (unsigned long long)t.x);
                    FMA2(a1, wp, (unsigned long long)t.y);
                }
            }
            if (!IS_N) {
                float f0, f1, f2, f3;
                UNPACK2(f0, f1, a0); UNPACK2(f2, f3, a1);
                float4 g = { sigm(f0), sigm(f1), sigm(f2), sigm(f3) };
                if (lane < HID) gwr[lane] = g;
            }
        }
        if (IS_N) {
            BAR_SYNC(BARID, 96);            // wait r,z of this layer
            if (act) {
                float4 r  = rb_l[hc];
                float4 z  = zb_l[hc];
                float4 hp = hb[(k + 1) & 1][hc];
                float ax0, ax1, ax2, ax3, ah0, ah1, ah2, ah3;
                UNPACK2(ax0, ax1, a0); UNPACK2(ax2, ax3, a1);
                UNPACK2(ah0, ah1, b0); UNPACK2(ah2, ah3, b1);
                float n0 = tanh_f(fmaf(r.x, ah0, ax0));
                float n1 = tanh_f(fmaf(r.y, ah1, ax1));
                float n2 = tanh_f(fmaf(r.z, ah2, ax2));
                float n3 = tanh_f(fmaf(r.w, ah3, ax3));
                float4 hn;
                hn.x = n0 + z.x * (hp.x - n0);
                hn.y = n1 + z.y * (hp.y - n1);
                hn.z = n2 + z.z * (hp.z - n2);
                hn.w = n3 + z.w * (hp.w - n3);
                if (lane < HID) hb[k & 1][lane] = hn;
            }
        } else {
            BAR_ARRIVE(BARID, 96);          // non-blocking: producers move on
        }
        BAR_SYNC(0, NTHR);                  // single global barrier per step
    }
}

// FC (t = k-4) + x prefetcher: ring of 4, distance 3 (LDG x(k+4) at iter k,
// publish x(k+3) at iter k; consumed by layer 1 at iter k+3).
static __device__ void fc_warp(
    const float* __restrict__ fcw, const float* __restrict__ fcb,
    const float* __restrict__ x,   float* __restrict__ out,
    int bbase, int lane,
    const float4 (*hb4)[32], float4 (*xb)[32])
{
    const int c10 = (lane < 10) ? lane : 0;
    float w[16];
#pragma unroll
    for (int c = 0; c < 16; ++c) w[c] = __ldg(fcw + c10 * 16 + c);
    const float bfc = __ldg(fcb + c10);

    // pend holds x(3) on loop entry (x(0..2) pre-published by main).
    float4 pend;
    {
        size_t off = (size_t)3 * 32 + lane;
        pend.x = __ldg(x + (size_t)(bbase + 0) * T_LEN * 32 + off);
        pend.y = __ldg(x + (size_t)(bbase + 1) * T_LEN * 32 + off);
        pend.z = __ldg(x + (size_t)(bbase + 2) * T_LEN * 32 + off);
        pend.w = __ldg(x + (size_t)(bbase + 3) * T_LEN * 32 + off);
    }

    for (int k = 0; k < T_LEN + 4; ++k) {
        if (k + 3 < T_LEN) xb[(k + 3) & 3][lane] = pend;   // publish x(k+3)
        if (k + 4 < T_LEN) {                               // fetch x(k+4)
            size_t off = (size_t)(k + 4) * 32 + lane;
            pend.x = __ldg(x + (size_t)(bbase + 0) * T_LEN * 32 + off);
            pend.y = __ldg(x + (size_t)(bbase + 1) * T_LEN * 32 + off);
            pend.z = __ldg(x + (size_t)(bbase + 2) * T_LEN * 32 + off);
            pend.w = __ldg(x + (size_t)(bbase + 3) * T_LEN * 32 + off);
        }
        const int t = k - 4;
        if (t >= 0) {
            const float4* h4 = hb4[(k + 1) & 1];
            float4 acc = { bfc, bfc, bfc, bfc };
#pragma unroll
            for (int c = 0; c < 16; ++c) {
                float4 v = h4[c];
                acc.x = fmaf(w[c], v.x, acc.x);
                acc.y = fmaf(w[c], v.y, acc.y);
                acc.z = fmaf(w[c], v.z, acc.z);
                acc.w = fmaf(w[c], v.w, acc.w);
            }
            if (lane < 10) {
                size_t base = ((size_t)bbase * 10 + lane) * T_LEN + t;
                out[base]                      = acc.x;
                out[base + 10 * (size_t)T_LEN] = acc.y;
                out[base + 20 * (size_t)T_LEN] = acc.z;
                out[base + 30 * (size_t)T_LEN] = acc.w;
            }
        }
        BAR_SYNC(0, NTHR);
    }
}

__global__ void __launch_bounds__(NTHR, 1)
gru_ae_pipe2_kernel(const float* __restrict__ x,
                    const float* __restrict__ fcw,  const float* __restrict__ fcb,
                    const float* __restrict__ wih1, const float* __restrict__ whh1,
                    const float* __restrict__ bih1, const float* __restrict__ bhh1,
                    const float* __restrict__ wih2, const float* __restrict__ whh2,
                    const float* __restrict__ bih2, const float* __restrict__ bhh2,
                    const float* __restrict__ wih3, const float* __restrict__ whh3,
                    const float* __restrict__ bih3, const float* __restrict__ bhh3,
                    const float* __restrict__ wih4, const float* __restrict__ whh4,
                    const float* __restrict__ bih4, const float* __restrict__ bhh4,
                    float* __restrict__ out)
{
    __shared__ float4 xb[4][32];
    __shared__ float4 hb1[2][32], hb2[2][32], hb3[2][32], hb4[2][32];
    __shared__ float4 rb[4][32], zb[4][32];

    const int tid   = threadIdx.x;
    const int wid   = tid >> 5;
    const int lane  = tid & 31;
    const int bbase = blockIdx.x * 4;

    {   // Zero h buffers (h(-1)=0; padded lanes stay 0 forever) + gates.
        float4 z4 = {0, 0, 0, 0};
        for (int i = tid; i < 64; i += NTHR) {
            (&hb1[0][0])[i] = z4; (&hb2[0][0])[i] = z4;
            (&hb3[0][0])[i] = z4; (&hb4[0][0])[i] = z4;
        }
        for (int i = tid; i < 128; i += NTHR) {
            (&rb[0][0])[i] = z4; (&zb[0][0])[i] = z4; (&xb[0][0])[i] = z4;
        }
    }
    __syncthreads();

    // Loader pre-publishes x(0..2) into ring slots 0..2.
    if (wid == 12) {
#pragma unroll
        for (int j = 0; j < 3; ++j) {
            size_t off = (size_t)j * 32 + lane;
            float4 xv;
            xv.x = __ldg(x + (size_t)(bbase + 0) * T_LEN * 32 + off);
            xv.y = __ldg(x + (size_t)(bbase + 1) * T_LEN * 32 + off);
            xv.z = __ldg(x + (size_t)(bbase + 2) * T_LEN * 32 + off);
            xv.w = __ldg(x + (size_t)(bbase + 3) * T_LEN * 32 + off);
            xb[j][lane] = xv;
        }
    }
    __syncthreads();

    // Role dispatch. Gate warps: 1 named barrier op + 1 global bar per iter.
    if      (wid == 0)  gate_warp<32, 30, false, true , 1>(wih1, whh1, bih1, bhh1, 0, lane, 0, xb,  hb1, rb[0], rb[0], zb[0]);
    else if (wid == 1)  gate_warp<32, 30, false, true , 1>(wih1, whh1, bih1, bhh1, 1, lane, 0, xb,  hb1, zb[0], rb[0], zb[0]);
    else if (wid == 2)  gate_warp<32, 30, true , true , 1>(wih1, whh1, bih1, bhh1, 2, lane, 0, xb,  hb1, rb[0], rb[0], zb[0]);
    else if (wid == 3)  gate_warp<30, 15, false, false, 2>(wih2, whh2, bih2, bhh2, 0, lane, 1, hb1, hb2, rb[1], rb[1], zb[1]);
    else if (wid == 4)  gate_warp<30, 15, false, false, 2>(wih2, whh2, bih2, bhh2, 1, lane, 1, hb1, hb2, zb[1], rb[1], zb[1]);
    else if (wid == 5)  gate_warp<30, 15, true , false, 2>(wih2, whh2, bih2, bhh2, 2, lane, 1, hb1, hb2, rb[1], rb[1], zb[1]);
    else if (wid == 6)  gate_warp<15, 30, false, false, 3>(wih3, whh3, bih3, bhh3, 0, lane, 2, hb2, hb3, rb[2], rb[2], zb[2]);
    else if (wid == 7)  gate_warp<15, 30, false, false, 3>(wih3, whh3, bih3, bhh3, 1, lane, 2, hb2, hb3, zb[2], rb[2], zb[2]);
    else if (wid == 8)  gate_warp<15, 30, true , false, 3>(wih3, whh3, bih3, bhh3, 2, lane, 2, hb2, hb3, rb[2], rb[2], zb[2]);
    else if (wid == 9)  gate_warp<30, 16, false, false, 4>(wih4, whh4, bih4, bhh4, 0, lane, 3, hb3, hb4, rb[3], rb[3], zb[3]);
    else if (wid == 10) gate_warp<30, 16, false, false, 4>(wih4, whh4, bih4, bhh4, 1, lane, 3, hb3, hb4, zb[3], rb[3], zb[3]);
    else if (wid == 11) gate_warp<30, 16, true , false, 4>(wih4, whh4, bih4, bhh4, 2, lane, 3, hb3, hb4, rb[3], rb[3], zb[3]);
    else                fc_warp(fcw, fcb, x, out, bbase, lane, hb4, xb);
}

extern "C" void kernel_launch(void* const* d_in, const int* in_sizes, int n_in,
                              void* d_out, int out_size) {
    (void)in_sizes; (void)n_in; (void)out_size;
    const float* x    = (const float*)d_in[0];
    const float* fcw  = (const float*)d_in[1];
    const float* fcb  = (const float*)d_in[2];
    const float* wih1 = (const float*)d_in[3];
    const float* whh1 = (const float*)d_in[4];
    const float* bih1 = (const float*)d_in[5];
    const float* bhh1 = (const float*)d_in[6];
    const float* wih2 = (const float*)d_in[7];
    const float* whh2 = (const float*)d_in[8];
    const float* bih2 = (const float*)d_in[9];
    const float* bhh2 = (const float*)d_in[10];
    const float* wih3 = (const float*)d_in[11];
    const float* whh3 = (const float*)d_in[12];
    const float* bih3 = (const float*)d_in[13];
    const float* bhh3 = (const float*)d_in[14];
    const float* wih4 = (const float*)d_in[15];
    const float* whh4 = (const float*)d_in[16];
    const float* bih4 = (const float*)d_in[17];
    const float* bhh4 = (const float*)d_in[18];
    float* out = (float*)d_out;

    gru_ae_pipe2_kernel<<<NBLK, NTHR>>>(
        x, fcw, fcb,
        wih1, whh1, bih1, bhh1,
        wih2, whh2, bih2, bhh2,
        wih3, whh3, bih3, bhh3,
        wih4, whh4, bih4, bhh4,
        out);
}

// round 6
// speedup vs baseline: 2.6535x; 1.0287x over previous
#include <cuda_runtime.h>
#include <cstddef>

// GRU_AE fused: one warp per LAYER (all 3 gates in-lane), 5 warps/block.
//   wid 0..3 : layer 1..4  (lane = hidden unit; r/z/n accs for 4 batches per lane)
//   wid 4    : FC + x loader (ring-4 prefetch)
// Weights pre-packed in smem as duplicated float2, transposed [gate][col][unit]:
// lane-consecutive LDS.64 feeds fma.rn.f32x2 with no PACK movs, no index ALU
// (full unroll -> immediate offsets). One global barrier per timestep; the GRU
// combine is lane-local (no cross-warp exchange at all).

#define T_LEN 2048
#define NTHR  160   // 5 warps
#define NBLK  128   // * 4 batches = 512

#define BAR() asm volatile("bar.sync 0, %0;" :: "n"(NTHR) : "memory")
#define PACK2(d, s)      asm("mov.b64 %0, {%1, %1};" : "=l"(d) : "f"(s))
#define UNPACK2(a, b, s) asm("mov.b64 {%0, %1}, %2;" : "=f"(a), "=f"(b) : "l"(s))
#define FMA2(acc, w, v)  asm("fma.rn.f32x2 %0, %1, %2, %0;" : "+l"(acc) : "l"(w), "l"(v))

struct Smem {
    float4 xb[4][32];        // x ring (distance-3 prefetch)
    float4 hb1[2][32];       // double-buffered hidden states, [col][4 batches]
    float4 hb2[2][32];
    float4 hb3[2][32];
    float4 hb4[2][32];
    float2 pw1[3][62][30];   // [gate][col][unit], value duplicated in .x/.y
    float2 pw2[3][45][15];
    float2 pw3[3][45][30];
    float2 pw4[3][46][16];
};

static __device__ __forceinline__ float sigm(float x) {
    return __fdividef(1.0f, 1.0f + __expf(-x));
}
static __device__ __forceinline__ float tanh_f(float x) {
    float e = __expf(2.0f * x);
    return 1.0f - __fdividef(2.0f, e + 1.0f);
}

// Stage one layer's weights into packed-transposed smem: dst[g][c][h] with
// c < IN from w_ih[:, c], else from w_hh[:, c-IN]; value duplicated into float2.
template <int IN, int HID>
static __device__ void stage(float2* dst, const float* __restrict__ wih,
                             const float* __restrict__ whh, int tid) {
    const int COLS = IN + HID;
    for (int i = tid; i < 3 * COLS * HID; i += NTHR) {
        int h = i % HID;
        int gc = i / HID;
        int c = gc % COLS;
        int g = gc / COLS;
        float v = (c < IN) ? wih[(g * HID + h) * IN + c]
                           : whh[(g * HID + h) * HID + (c - IN)];
        dst[i] = make_float2(v, v);
    }
}

// One layer warp for the whole run. delay = layer index (pipeline skew).
// At iter k (if active): h_new(k-delay) from input vb and own hb, both read at
// slot (k+1)&1 (or x ring slot k&3), written to hb[k&1].
template <int IN, int HID, bool XRING>
static __device__ void layer_warp(
    const float2* __restrict__ pw,                   // [3][IN+HID][HID]
    const float* __restrict__ bih, const float* __restrict__ bhh,
    const float4 (*vb)[32], float4 (*hb)[32],
    int lane, int delay)
{
    const int COLS = IN + HID;
    const int hc = (lane < HID) ? lane : 0;

    const float2* pr = pw + (size_t)(0 * COLS) * HID + hc;
    const float2* pz = pw + (size_t)(1 * COLS) * HID + hc;
    const float2* pn = pw + (size_t)(2 * COLS) * HID + hc;

    unsigned long long pbr, pbz, pbm, pbn;
    {
        float br = __ldg(bih + 0 * HID + hc) + __ldg(bhh + 0 * HID + hc);
        float bz = __ldg(bih + 1 * HID + hc) + __ldg(bhh + 1 * HID + hc);
        float bm = __ldg(bih + 2 * HID + hc);   // b_ih_n (x side)
        float bn = __ldg(bhh + 2 * HID + hc);   // b_hh_n (h side, inside r*)
        PACK2(pbr, br); PACK2(pbz, bz); PACK2(pbm, bm); PACK2(pbn, bn);
    }

    float4 hp = {0.f, 0.f, 0.f, 0.f};   // own unit's h_prev, 4 batches

    for (int k = 0; k < T_LEN + 4; ++k) {
        const int s = k - delay;
        const bool act = (s >= 0) && (s < T_LEN);
        if (act) {
            unsigned long long r0 = pbr, r1 = pbr, z0 = pbz, z1 = pbz;
            unsigned long long m0 = pbm, m1 = pbm, n0 = pbn, n1 = pbn;
            const float4* v = XRING ? vb[k & 3] : vb[(k + 1) & 1];
            const float4* h = hb[(k + 1) & 1];
#pragma unroll
            for (int c = 0; c < IN; ++c) {
                longlong2 t = *(const longlong2*)(v + c);              // broadcast
                unsigned long long wr = *(const unsigned long long*)(pr + c * HID);
                unsigned long long wz = *(const unsigned long long*)(pz + c * HID);
                unsigned long long wn = *(const unsigned long long*)(pn + c * HID);
                FMA2(r0, wr, (unsigned long long)t.x); FMA2(r1, wr, (unsigned long long)t.y);
                FMA2(z0, wz, (unsigned long long)t.x); FMA2(z1, wz, (unsigned long long)t.y);
                FMA2(m0, wn, (unsigned long long)t.x); FMA2(m1, wn, (unsigned long long)t.y);
            }
#pragma unroll
            for (int c = 0; c < HID; ++c) {
                longlong2 t = *(const longlong2*)(h + c);              // broadcast
                unsigned long long wr = *(const unsigned long long*)(pr + (IN + c) * HID);
                unsigned long long wz = *(const unsigned long long*)(pz + (IN + c) * HID);
                unsigned long long wn = *(const unsigned long long*)(pn + (IN + c) * HID);
                FMA2(r0, wr, (unsigned long long)t.x); FMA2(r1, wr, (unsigned long long)t.y);
                FMA2(z0, wz, (unsigned long long)t.x); FMA2(z1, wz, (unsigned long long)t.y);
                FMA2(n0, wn, (unsigned long long)t.x); FMA2(n1, wn, (unsigned long long)t.y);
            }
            float ra, rb, rc, rd, za, zbv, zc, zd;
            float ma, mb, mc, md, na, nb, nc, nd;
            UNPACK2(ra, rb, r0); UNPACK2(rc, rd, r1);
            UNPACK2(za, zbv, z0); UNPACK2(zc, zd, z1);
            UNPACK2(ma, mb, m0); UNPACK2(mc, md, m1);
            UNPACK2(na, nb, n0); UNPACK2(nc, nd, n1);
            ra = sigm(ra); rb = sigm(rb); rc = sigm(rc); rd = sigm(rd);
            za = sigm(za); zbv = sigm(zbv); zc = sigm(zc); zd = sigm(zd);
            float A = tanh_f(fmaf(ra, na, ma));
            float Bv = tanh_f(fmaf(rb, nb, mb));
            float C = tanh_f(fmaf(rc, nc, mc));
            float D = tanh_f(fmaf(rd, nd, md));
            float4 hn;
            hn.x = A  + za  * (hp.x - A);
            hn.y = Bv + zbv * (hp.y - Bv);
            hn.z = C  + zc  * (hp.z - C);
            hn.w = D  + zd  * (hp.w - D);
            if (lane < HID) hb[k & 1][lane] = hn;
            hp = hn;
        }
        BAR();
    }
}

// Warp 4: FC (t = k-4, reads hb4 slot (k+1)&1) + x prefetch (ring-4, distance 3).
static __device__ void fc_loader_warp(
    const float* __restrict__ fcw, const float* __restrict__ fcb,
    const float* __restrict__ x,   float* __restrict__ out,
    int bbase, int lane,
    const float4 (*hb4)[32], float4 (*xb)[32])
{
    const int c10 = (lane < 10) ? lane : 0;
    float w[16];
#pragma unroll
    for (int c = 0; c < 16; ++c) w[c] = __ldg(fcw + c10 * 16 + c);
    const float bfc = __ldg(fcb + c10);

    float4 pend;   // holds x(3) on loop entry (x(0..2) pre-published by main)
    {
        size_t off = (size_t)3 * 32 + lane;
        pend.x = __ldg(x + (size_t)(bbase + 0) * T_LEN * 32 + off);
        pend.y = __ldg(x + (size_t)(bbase + 1) * T_LEN * 32 + off);
        pend.z = __ldg(x + (size_t)(bbase + 2) * T_LEN * 32 + off);
        pend.w = __ldg(x + (size_t)(bbase + 3) * T_LEN * 32 + off);
    }

    for (int k = 0; k < T_LEN + 4; ++k) {
        if (k + 3 < T_LEN) xb[(k + 3) & 3][lane] = pend;   // publish x(k+3)
        if (k + 4 < T_LEN) {                               // fetch x(k+4)
            size_t off = (size_t)(k + 4) * 32 + lane;
            pend.x = __ldg(x + (size_t)(bbase + 0) * T_LEN * 32 + off);
            pend.y = __ldg(x + (size_t)(bbase + 1) * T_LEN * 32 + off);
            pend.z = __ldg(x + (size_t)(bbase + 2) * T_LEN * 32 + off);
            pend.w = __ldg(x + (size_t)(bbase + 3) * T_LEN * 32 + off);
        }
        const int t = k - 4;
        if (t >= 0) {
            const float4* h4 = hb4[(k + 1) & 1];
            float4 acc = { bfc, bfc, bfc, bfc };
#pragma unroll
            for (int c = 0; c < 16; ++c) {
                float4 v = h4[c];
                acc.x = fmaf(w[c], v.x, acc.x);
                acc.y = fmaf(w[c], v.y, acc.y);
                acc.z = fmaf(w[c], v.z, acc.z);
                acc.w = fmaf(w[c], v.w, acc.w);
            }
            if (lane < 10) {
                size_t base = ((size_t)bbase * 10 + lane) * T_LEN + t;
                out[base]                      = acc.x;
                out[base + 10 * (size_t)T_LEN] = acc.y;
                out[base + 20 * (size_t)T_LEN] = acc.z;
                out[base + 30 * (size_t)T_LEN] = acc.w;
            }
        }
        BAR();
    }
}

__global__ void __launch_bounds__(NTHR, 1)
gru_ae_fat_kernel(const float* __restrict__ x,
                  const float* __restrict__ fcw,  const float* __restrict__ fcb,
                  const float* __restrict__ wih1, const float* __restrict__ whh1,
                  const float* __restrict__ bih1, const float* __restrict__ bhh1,
                  const float* __restrict__ wih2, const float* __restrict__ whh2,
                  const float* __restrict__ bih2, const float* __restrict__ bhh2,
                  const float* __restrict__ wih3, const float* __restrict__ whh3,
                  const float* __restrict__ bih3, const float* __restrict__ bhh3,
                  const float* __restrict__ wih4, const float* __restrict__ whh4,
                  const float* __restrict__ bih4, const float* __restrict__ bhh4,
                  float* __restrict__ out)
{
    extern __shared__ char raw[];
    Smem* sm = (Smem*)raw;

    const int tid   = threadIdx.x;
    const int wid   = tid >> 5;
    const int lane  = tid & 31;
    const int bbase = blockIdx.x * 4;

    // Stage packed weights + zero the vector buffers.
    stage<32, 30>(&sm->pw1[0][0][0], wih1, whh1, tid);
    stage<30, 15>(&sm->pw2[0][0][0], wih2, whh2, tid);
    stage<15, 30>(&sm->pw3[0][0][0], wih3, whh3, tid);
    stage<30, 16>(&sm->pw4[0][0][0], wih4, whh4, tid);
    {
        float4 z4 = {0, 0, 0, 0};
        for (int i = tid; i < 4 * 32; i += NTHR) (&sm->xb[0][0])[i] = z4;
        for (int i = tid; i < 2 * 32; i += NTHR) {
            sm->hb1[0][i & 31] = z4; sm->hb1[1][i & 31] = z4;
        }
        for (int i = tid; i < 64; i += NTHR) {
            (&sm->hb1[0][0])[i] = z4; (&sm->hb2[0][0])[i] = z4;
            (&sm->hb3[0][0])[i] = z4; (&sm->hb4[0][0])[i] = z4;
        }
    }
    __syncthreads();

    // Loader pre-publishes x(0..2) into ring slots 0..2.
    if (wid == 4) {
#pragma unroll
        for (int j = 0; j < 3; ++j) {
            size_t off = (size_t)j * 32 + lane;
            float4 xv;
            xv.x = __ldg(x + (size_t)(bbase + 0) * T_LEN * 32 + off);
            xv.y = __ldg(x + (size_t)(bbase + 1) * T_LEN * 32 + off);
            xv.z = __ldg(x + (size_t)(bbase + 2) * T_LEN * 32 + off);
            xv.w = __ldg(x + (size_t)(bbase + 3) * T_LEN * 32 + off);
            sm->xb[j][lane] = xv;
        }
    }
    __syncthreads();

    if      (wid == 0) layer_warp<32, 30, true >(&sm->pw1[0][0][0], bih1, bhh1, sm->xb,  sm->hb1, lane, 0);
    else if (wid == 1) layer_warp<30, 15, false>(&sm->pw2[0][0][0], bih2, bhh2, sm->hb1, sm->hb2, lane, 1);
    else if (wid == 2) layer_warp<15, 30, false>(&sm->pw3[0][0][0], bih3, bhh3, sm->hb2, sm->hb3, lane, 2);
    else if (wid == 3) layer_warp<30, 16, false>(&sm->pw4[0][0][0], bih4, bhh4, sm->hb3, sm->hb4, lane, 3);
    else               fc_loader_warp(fcw, fcb, x, out, bbase, lane, sm->hb4, sm->xb);
}

extern "C" void kernel_launch(void* const* d_in, const int* in_sizes, int n_in,
                              void* d_out, int out_size) {
    (void)in_sizes; (void)n_in; (void)out_size;
    const float* x    = (const float*)d_in[0];
    const float* fcw  = (const float*)d_in[1];
    const float* fcb  = (const float*)d_in[2];
    const float* wih1 = (const float*)d_in[3];
    const float* whh1 = (const float*)d_in[4];
    const float* bih1 = (const float*)d_in[5];
    const float* bhh1 = (const float*)d_in[6];
    const float* wih2 = (const float*)d_in[7];
    const float* whh2 = (const float*)d_in[8];
    const float* bih2 = (const float*)d_in[9];
    const float* bhh2 = (const float*)d_in[10];
    const float* wih3 = (const float*)d_in[11];
    const float* whh3 = (const float*)d_in[12];
    const float* bih3 = (const float*)d_in[13];
    const float* bhh3 = (const float*)d_in[14];
    const float* wih4 = (const float*)d_in[15];
    const float* whh4 = (const float*)d_in[16];
    const float* bih4 = (const float*)d_in[17];
    const float* bhh4 = (const float*)d_in[18];
    float* out = (float*)d_out;

    cudaFuncSetAttribute(gru_ae_fat_kernel,
                         cudaFuncAttributeMaxDynamicSharedMemorySize,
                         (int)sizeof(Smem));

    gru_ae_fat_kernel<<<NBLK, NTHR, sizeof(Smem)>>>(
        x, fcw, fcb,
        wih1, whh1, bih1, bhh1,
        wih2, whh2, bih2, bhh2,
        wih3, whh3, bih3, bhh3,
        wih4, whh4, bih4, bhh4,
        out);
}

// round 7
// speedup vs baseline: 6.1116x; 2.3032x over previous
#include <cuda_runtime.h>
#include <cstddef>

// GRU_AE fused, layer-pipelined with K=4 timesteps per barrier interval.
// 5 warps/block, 4 batches/block, 128 blocks (single wave).
//   wid 0: layer 2, wid 1: layer 1, wid 2: layer 3, wid 3: layer 4, wid 4: FC+x
// Interval m: layer L computes steps 4(m-L)+j (j=0..3). Producer writes its 4
// outputs at parity m&1; consumer reads parity (m-1)&1. ONE bar.sync per
// interval (per 4 timesteps). Inside an interval the h recurrence is
// warp-private (STS + __syncwarp + LDS, no block barrier).
// x-side dots for the 4 steps are computed as one ILP block with each weight
// register-reused 12x (3 gates impossible—per gate: 4 steps x 4 batches).

#define T_LEN 2048
#define NTHR  160
#define NBLK  128
#define KS    4
#define NINT  516   // 512 intervals + 4 pipeline drain

#define BAR() asm volatile("bar.sync 0, %0;" :: "n"(NTHR) : "memory")

struct Smem {
    float4 xb [2][KS][32];
    float4 hb1[2][KS][32];
    float4 hb2[2][KS][32];
    float4 hb3[2][KS][32];
    float4 hb4[2][KS][32];
    float  wt1[3][62][32];   // [gate][col][unit] ; col < IN from w_ih, else w_hh
    float  wt2[3][45][32];
    float  wt3[3][45][32];
    float  wt4[3][46][32];
};

static __device__ __forceinline__ float sigm(float x) {
    return __fdividef(1.0f, 1.0f + __expf(-x));
}
static __device__ __forceinline__ float tanh_f(float x) {
    float e = __expf(2.0f * x);
    return 1.0f - __fdividef(2.0f, e + 1.0f);
}

template <int IN, int HID>
static __device__ void stage(float* dst, const float* __restrict__ wih,
                             const float* __restrict__ whh, int tid) {
    const int COLS = IN + HID;
    for (int i = tid; i < 3 * COLS * HID; i += NTHR) {
        int u = i % HID;
        int gc = i / HID;
        int c = gc % COLS;
        int g = gc / COLS;
        float v = (c < IN) ? wih[(g * HID + u) * IN + c]
                           : whh[(g * HID + u) * HID + (c - IN)];
        dst[(g * COLS + c) * 32 + u] = v;
    }
}

template <int IN, int HID, int DELAY>
static __device__ void layer_warp(
    const float* __restrict__ wt,                    // [3][IN+HID][32]
    const float* __restrict__ bih, const float* __restrict__ bhh,
    const float4 (*vb)[KS][32], float4 (*hb)[KS][32], int lane)
{
    const int COLS = IN + HID;
    const int hc = (lane < HID) ? lane : 0;
    const float br = __ldg(bih + hc)           + __ldg(bhh + hc);
    const float bz = __ldg(bih + HID + hc)     + __ldg(bhh + HID + hc);
    const float bm = __ldg(bih + 2 * HID + hc);            // b_ih_n
    const float bn = __ldg(bhh + 2 * HID + hc);            // b_hh_n

    const float* wr0 = wt + (0 * COLS) * 32 + hc;
    const float* wz0 = wt + (1 * COLS) * 32 + hc;
    const float* wn0 = wt + (2 * COLS) * 32 + hc;

    float4 hp = {0.f, 0.f, 0.f, 0.f};    // own unit's h_prev, 4 batches

    for (int m = 0; m < NINT; ++m) {
        const int p = m & 1;
        if (m >= DELAY && m < DELAY + T_LEN / KS) {
            // ---- x-side: 4 independent steps, weight reused 12x per load ----
            float4 axr[KS], axz[KS], axn[KS];
#pragma unroll
            for (int j = 0; j < KS; ++j) {
                axr[j] = make_float4(br, br, br, br);
                axz[j] = make_float4(bz, bz, bz, bz);
                axn[j] = make_float4(bm, bm, bm, bm);
            }
#pragma unroll 4
            for (int c = 0; c < IN; ++c) {
                float wr = wr0[c * 32];
                float wz = wz0[c * 32];
                float wn = wn0[c * 32];
#pragma unroll
                for (int j = 0; j < KS; ++j) {
                    float4 v = vb[1 - p][j][c];
                    axr[j].x = fmaf(wr, v.x, axr[j].x);
                    axr[j].y = fmaf(wr, v.y, axr[j].y);
                    axr[j].z = fmaf(wr, v.z, axr[j].z);
                    axr[j].w = fmaf(wr, v.w, axr[j].w);
                    axz[j].x = fmaf(wz, v.x, axz[j].x);
                    axz[j].y = fmaf(wz, v.y, axz[j].y);
                    axz[j].z = fmaf(wz, v.z, axz[j].z);
                    axz[j].w = fmaf(wz, v.w, axz[j].w);
                    axn[j].x = fmaf(wn, v.x, axn[j].x);
                    axn[j].y = fmaf(wn, v.y, axn[j].y);
                    axn[j].z = fmaf(wn, v.z, axn[j].z);
                    axn[j].w = fmaf(wn, v.w, axn[j].w);
                }
            }
            // ---- h-side + combine, serial over the 4 steps (warp-private) ----
#pragma unroll
            for (int j = 0; j < KS; ++j) {
                float4 ar = axr[j], az = axz[j];
                float4 an = make_float4(bn, bn, bn, bn);
                const float4* hv = (j == 0) ? hb[1 - p][KS - 1] : hb[p][j - 1];
#pragma unroll 5
                for (int c = 0; c < HID; ++c) {
                    float wr = wr0[(IN + c) * 32];
                    float wz = wz0[(IN + c) * 32];
                    float wn = wn0[(IN + c) * 32];
                    float4 h = hv[c];
                    ar.x = fmaf(wr, h.x, ar.x); ar.y = fmaf(wr, h.y, ar.y);
                    ar.z = fmaf(wr, h.z, ar.z); ar.w = fmaf(wr, h.w, ar.w);
                    az.x = fmaf(wz, h.x, az.x); az.y = fmaf(wz, h.y, az.y);
                    az.z = fmaf(wz, h.z, az.z); az.w = fmaf(wz, h.w, az.w);
                    an.x = fmaf(wn, h.x, an.x); an.y = fmaf(wn, h.y, an.y);
                    an.z = fmaf(wn, h.z, an.z); an.w = fmaf(wn, h.w, an.w);
                }
                float4 r, z, n;
                r.x = sigm(ar.x); r.y = sigm(ar.y); r.z = sigm(ar.z); r.w = sigm(ar.w);
                z.x = sigm(az.x); z.y = sigm(az.y); z.z = sigm(az.z); z.w = sigm(az.w);
                n.x = tanh_f(fmaf(r.x, an.x, axn[j].x));
                n.y = tanh_f(fmaf(r.y, an.y, axn[j].y));
                n.z = tanh_f(fmaf(r.z, an.z, axn[j].z));
                n.w = tanh_f(fmaf(r.w, an.w, axn[j].w));
                float4 hn;
                hn.x = n.x + z.x * (hp.x - n.x);
                hn.y = n.y + z.y * (hp.y - n.y);
                hn.z = n.z + z.z * (hp.z - n.z);
                hn.w = n.w + z.w * (hp.w - n.w);
                hp = hn;
                if (lane < HID) hb[p][j][lane] = hn;
                __syncwarp();          // order STS before next step's LDS
            }
        }
        BAR();                         // one barrier per 4 timesteps
    }
}

// Warp 4: FC for steps 4(m-4)+j + x loader for interval m+1.
static __device__ void fc_warp(
    const float* __restrict__ fcw, const float* __restrict__ fcb,
    const float* __restrict__ x,   float* __restrict__ out,
    int bbase, int lane,
    const float4 (*hb4)[KS][32], float4 (*xb)[KS][32])
{
    const int c10 = (lane < 10) ? lane : 0;
    float w[16];
#pragma unroll
    for (int c = 0; c < 16; ++c) w[c] = __ldg(fcw + c10 * 16 + c);
    const float bfc = __ldg(fcb + c10);

    for (int m = 0; m < NINT; ++m) {
        const int p = m & 1;
        // Load x for interval m+1 (steps 4(m+1)+j) into parity p.
#pragma unroll
        for (int j = 0; j < KS; ++j) {
            int s = KS * (m + 1) + j;
            if (s < T_LEN) {
                size_t off = (size_t)s * 32 + lane;
                float4 xv;
                xv.x = __ldg(x + (size_t)(bbase + 0) * T_LEN * 32 + off);
                xv.y = __ldg(x + (size_t)(bbase + 1) * T_LEN * 32 + off);
                xv.z = __ldg(x + (size_t)(bbase + 2) * T_LEN * 32 + off);
                xv.w = __ldg(x + (size_t)(bbase + 3) * T_LEN * 32 + off);
                xb[p][j][lane] = xv;
            }
        }
        if (m >= 4) {
#pragma unroll
            for (int j = 0; j < KS; ++j) {
                int t = KS * (m - 4) + j;
                const float4* h4 = hb4[1 - p][j];
                float4 acc = make_float4(bfc, bfc, bfc, bfc);
#pragma unroll
                for (int c = 0; c < 16; ++c) {
                    float4 v = h4[c];
                    acc.x = fmaf(w[c], v.x, acc.x);
                    acc.y = fmaf(w[c], v.y, acc.y);
                    acc.z = fmaf(w[c], v.z, acc.z);
                    acc.w = fmaf(w[c], v.w, acc.w);
                }
                if (lane < 10) {
                    size_t base = ((size_t)bbase * 10 + lane) * T_LEN + t;
                    out[base]                      = acc.x;
                    out[base + 10 * (size_t)T_LEN] = acc.y;
                    out[base + 20 * (size_t)T_LEN] = acc.z;
                    out[base + 30 * (size_t)T_LEN] = acc.w;
                }
            }
        }
        BAR();
    }
}

__global__ void __launch_bounds__(NTHR, 1)
gru_ae_k4_kernel(const float* __restrict__ x,
                 const float* __restrict__ fcw,  const float* __restrict__ fcb,
                 const float* __restrict__ wih1, const float* __restrict__ whh1,
                 const float* __restrict__ bih1, const float* __restrict__ bhh1,
                 const float* __restrict__ wih2, const float* __restrict__ whh2,
                 const float* __restrict__ bih2, const float* __restrict__ bhh2,
                 const float* __restrict__ wih3, const float* __restrict__ whh3,
                 const float* __restrict__ bih3, const float* __restrict__ bhh3,
                 const float* __restrict__ wih4, const float* __restrict__ whh4,
                 const float* __restrict__ bih4, const float* __restrict__ bhh4,
                 float* __restrict__ out)
{
    extern __shared__ char raw[];
    Smem* sm = (Smem*)raw;

    const int tid   = threadIdx.x;
    const int wid   = tid >> 5;
    const int lane  = tid & 31;
    const int bbase = blockIdx.x * 4;

    stage<32, 30>(&sm->wt1[0][0][0], wih1, whh1, tid);
    stage<30, 15>(&sm->wt2[0][0][0], wih2, whh2, tid);
    stage<15, 30>(&sm->wt3[0][0][0], wih3, whh3, tid);
    stage<30, 16>(&sm->wt4[0][0][0], wih4, whh4, tid);
    {
        float4 z4 = {0, 0, 0, 0};
        float4* bufs[5] = { &sm->xb[0][0][0], &sm->hb1[0][0][0], &sm->hb2[0][0][0],
                            &sm->hb3[0][0][0], &sm->hb4[0][0][0] };
#pragma unroll
        for (int b = 0; b < 5; ++b)
            for (int i = tid; i < 2 * KS * 32; i += NTHR) bufs[b][i] = z4;
    }
    __syncthreads();

    // Prelude: x steps 0..3 into xb[1] (consumed at interval 0 reading 1-p=1).
    if (wid == 4) {
#pragma unroll
        for (int j = 0; j < KS; ++j) {
            size_t off = (size_t)j * 32 + lane;
            float4 xv;
            xv.x = __ldg(x + (size_t)(bbase + 0) * T_LEN * 32 + off);
            xv.y = __ldg(x + (size_t)(bbase + 1) * T_LEN * 32 + off);
            xv.z = __ldg(x + (size_t)(bbase + 2) * T_LEN * 32 + off);
            xv.w = __ldg(x + (size_t)(bbase + 3) * T_LEN * 32 + off);
            sm->xb[1][j][lane] = xv;
        }
    }
    __syncthreads();

    // SMSP = wid % 4. Lightest layer (L2) shares SMSP0 with the FC warp.
    if      (wid == 0) layer_warp<30, 15, 1>(&sm->wt2[0][0][0], bih2, bhh2, sm->hb1, sm->hb2, lane);
    else if (wid == 1) layer_warp<32, 30, 0>(&sm->wt1[0][0][0], bih1, bhh1, sm->xb,  sm->hb1, lane);
    else if (wid == 2) layer_warp<15, 30, 2>(&sm->wt3[0][0][0], bih3, bhh3, sm->hb2, sm->hb3, lane);
    else if (wid == 3) layer_warp<30, 16, 3>(&sm->wt4[0][0][0], bih4, bhh4, sm->hb3, sm->hb4, lane);
    else               fc_warp(fcw, fcb, x, out, bbase, lane, sm->hb4, sm->xb);
}

extern "C" void kernel_launch(void* const* d_in, const int* in_sizes, int n_in,
                              void* d_out, int out_size) {
    (void)in_sizes; (void)n_in; (void)out_size;
    const float* x    = (const float*)d_in[0];
    const float* fcw  = (const float*)d_in[1];
    const float* fcb  = (const float*)d_in[2];
    const float* wih1 = (const float*)d_in[3];
    const float* whh1 = (const float*)d_in[4];
    const float* bih1 = (const float*)d_in[5];
    const float* bhh1 = (const float*)d_in[6];
    const float* wih2 = (const float*)d_in[7];
    const float* whh2 = (const float*)d_in[8];
    const float* bih2 = (const float*)d_in[9];
    const float* bhh2 = (const float*)d_in[10];
    const float* wih3 = (const float*)d_in[11];
    const float* whh3 = (const float*)d_in[12];
    const float* bih3 = (const float*)d_in[13];
    const float* bhh3 = (const float*)d_in[14];
    const float* wih4 = (const float*)d_in[15];
    const float* whh4 = (const float*)d_in[16];
    const float* bih4 = (const float*)d_in[17];
    const float* bhh4 = (const float*)d_in[18];
    float* out = (float*)d_out;

    cudaFuncSetAttribute(gru_ae_k4_kernel,
                         cudaFuncAttributeMaxDynamicSharedMemorySize,
                         (int)sizeof(Smem));

    gru_ae_k4_kernel<<<NBLK, NTHR, sizeof(Smem)>>>(
        x, fcw, fcb,
        wih1, whh1, bih1, bhh1,
        wih2, whh2, bih2, bhh2,
        wih3, whh3, bih3, bhh3,
        wih4, whh4, bih4, bhh4,
        out);
}

// round 9
// speedup vs baseline: 6.9477x; 1.1368x over previous
#include <cuda_runtime.h>
#include <cstddef>

// GRU_AE fused, layer-pipelined, K=8 timesteps per barrier interval,
// 2 batch elements per block, 256 blocks (single wave, ~2 blocks/SM so
// co-resident blocks hide each other's stalls).
//   wid 0: layer 2, wid 1: layer 1, wid 2: layer 3, wid 3: layer 4, wid 4: FC+x
// Interval m: layer L computes steps 8(m-L)+j (j=0..7). Producer writes parity
// m&1; consumer reads parity (m-1)&1. ONE bar.sync per 8 timesteps. Inside an
// interval the h recurrence is warp-private (STS + __syncwarp + LDS).

#define T_LEN 2048
#define NTHR  160
#define NBLK  256    // * 2 batches = 512
#define KS    8
#define NINT  (T_LEN / KS + 4)   // 260

#define BAR() asm volatile("bar.sync 0, %0;" :: "n"(NTHR) : "memory")

struct Smem {
    float2 xb [2][KS][32];
    float2 hb1[2][KS][32];
    float2 hb2[2][KS][32];
    float2 hb3[2][KS][32];
    float2 hb4[2][KS][32];
    float  wt1[3][62][32];   // [gate][col][unit-padded]
    float  wt2[3][45][16];
    float  wt3[3][45][32];
    float  wt4[3][46][16];
};

static __device__ __forceinline__ float sigm(float x) {
    return __fdividef(1.0f, 1.0f + __expf(-x));
}
static __device__ __forceinline__ float tanh_f(float x) {
    float e = __expf(2.0f * x);
    return 1.0f - __fdividef(2.0f, e + 1.0f);
}

template <int IN, int HID, int PAD>
static __device__ void stage(float* dst, const float* __restrict__ wih,
                             const float* __restrict__ whh, int tid) {
    const int COLS = IN + HID;
    for (int i = tid; i < 3 * COLS * HID; i += NTHR) {
        int u = i % HID;
        int gc = i / HID;
        int c = gc % COLS;
        int g = gc / COLS;
        float v = (c < IN) ? wih[(g * HID + u) * IN + c]
                           : whh[(g * HID + u) * HID + (c - IN)];
        dst[(g * COLS + c) * PAD + u] = v;
    }
}

template <int IN, int HID, int PAD, int DELAY>
static __device__ void layer_warp(
    const float* __restrict__ wt,                    // [3][IN+HID][PAD]
    const float* __restrict__ bih, const float* __restrict__ bhh,
    const float2 (*vb)[KS][32], float2 (*hb)[KS][32], int lane)
{
    const int COLS = IN + HID;
    const int hc = (lane < HID) ? lane : 0;
    const float br = __ldg(bih + hc)           + __ldg(bhh + hc);
    const float bz = __ldg(bih + HID + hc)     + __ldg(bhh + HID + hc);
    const float bm = __ldg(bih + 2 * HID + hc);            // b_ih_n
    const float bn = __ldg(bhh + 2 * HID + hc);            // b_hh_n

    const float* wr0 = wt + (0 * COLS) * PAD + hc;
    const float* wz0 = wt + (1 * COLS) * PAD + hc;
    const float* wn0 = wt + (2 * COLS) * PAD + hc;

    float2 hp = {0.f, 0.f};              // own unit's h_prev, 2 batches

    for (int m = 0; m < NINT; ++m) {
        const int p = m & 1;
        if (m >= DELAY && m < DELAY + T_LEN / KS) {
            // ---- x-side: 8 independent steps, weight reused 16x per load ----
            float2 axr[KS], axz[KS], axn[KS];
#pragma unroll
            for (int j = 0; j < KS; ++j) {
                axr[j] = make_float2(br, br);
                axz[j] = make_float2(bz, bz);
                axn[j] = make_float2(bm, bm);
            }
#pragma unroll 4
            for (int c = 0; c < IN; ++c) {
                float wr = wr0[c * PAD];
                float wz = wz0[c * PAD];
                float wn = wn0[c * PAD];
#pragma unroll
                for (int j = 0; j < KS; ++j) {
                    float2 v = vb[1 - p][j][c];
                    axr[j].x = fmaf(wr, v.x, axr[j].x);
                    axr[j].y = fmaf(wr, v.y, axr[j].y);
                    axz[j].x = fmaf(wz, v.x, axz[j].x);
                    axz[j].y = fmaf(wz, v.y, axz[j].y);
                    axn[j].x = fmaf(wn, v.x, axn[j].x);
                    axn[j].y = fmaf(wn, v.y, axn[j].y);
                }
            }
            // ---- h-side + combine, serial over the 8 steps (warp-private) ----
#pragma unroll
            for (int j = 0; j < KS; ++j) {
                float2 ar = axr[j], az = axz[j];
                float2 an = make_float2(bn, bn);
                const float2* hv = (j == 0) ? hb[1 - p][KS - 1] : hb[p][j - 1];
#pragma unroll 6
                for (int c = 0; c < HID; ++c) {
                    float wr = wr0[(IN + c) * PAD];
                    float wz = wz0[(IN + c) * PAD];
                    float wn = wn0[(IN + c) * PAD];
                    float2 h = hv[c];
                    ar.x = fmaf(wr, h.x, ar.x); ar.y = fmaf(wr, h.y, ar.y);
                    az.x = fmaf(wz, h.x, az.x); az.y = fmaf(wz, h.y, az.y);
                    an.x = fmaf(wn, h.x, an.x); an.y = fmaf(wn, h.y, an.y);
                }
                float rx = sigm(ar.x), ry = sigm(ar.y);
                float zx = sigm(az.x), zy = sigm(az.y);
                float nx = tanh_f(fmaf(rx, an.x, axn[j].x));
                float ny = tanh_f(fmaf(ry, an.y, axn[j].y));
                float2 hn;
                hn.x = nx + zx * (hp.x - nx);
                hn.y = ny + zy * (hp.y - ny);
                hp = hn;
                if (lane < HID) hb[p][j][lane] = hn;
                __syncwarp();          // order STS before next step's LDS
            }
        }
        BAR();                         // one barrier per 8 timesteps
    }
}

// Warp 4: FC for steps 8(m-4)+j + x loader for interval m+1.
static __device__ void fc_warp(
    const float* __restrict__ fcw, const float* __restrict__ fcb,
    const float* __restrict__ x,   float* __restrict__ out,
    int bbase, int lane,
    const float2 (*hb4)[KS][32], float2 (*xb)[KS][32])
{
    const int c10 = (lane < 10) ? lane : 0;
    float w[16];
#pragma unroll
    for (int c = 0; c < 16; ++c) w[c] = __ldg(fcw + c10 * 16 + c);
    const float bfc = __ldg(fcb + c10);

    for (int m = 0; m < NINT; ++m) {
        const int p = m & 1;
        // Load x for interval m+1 (steps 8(m+1)+j) into parity p.
#pragma unroll
        for (int j = 0; j < KS; ++j) {
            int s = KS * (m + 1) + j;
            if (s < T_LEN) {
                size_t off = (size_t)s * 32 + lane;
                float2 xv;
                xv.x = __ldg(x + (size_t)(bbase + 0) * T_LEN * 32 + off);
                xv.y = __ldg(x + (size_t)(bbase + 1) * T_LEN * 32 + off);
                xb[p][j][lane] = xv;
            }
        }
        if (m >= 4) {
#pragma unroll
            for (int j = 0; j < KS; ++j) {
                int t = KS * (m - 4) + j;
                const float2* h4 = hb4[1 - p][j];
                float2 acc = make_float2(bfc, bfc);
#pragma unroll
                for (int c = 0; c < 16; ++c) {
                    float2 v = h4[c];
                    acc.x = fmaf(w[c], v.x, acc.x);
                    acc.y = fmaf(w[c], v.y, acc.y);
                }
                if (lane < 10) {
                    size_t base = ((size_t)bbase * 10 + lane) * T_LEN + t;
                    out[base]                      = acc.x;
                    out[base + 10 * (size_t)T_LEN] = acc.y;
                }
            }
        }
        BAR();
    }
}

__global__ void __launch_bounds__(NTHR, 2)
gru_ae_k8_kernel(const float* __restrict__ x,
                 const float* __restrict__ fcw,  const float* __restrict__ fcb,
                 const float* __restrict__ wih1, const float* __restrict__ whh1,
                 const float* __restrict__ bih1, const float* __restrict__ bhh1,
                 const float* __restrict__ wih2, const float* __restrict__ whh2,
                 const float* __restrict__ bih2, const float* __restrict__ bhh2,
                 const float* __restrict__ wih3, const float* __restrict__ whh3,
                 const float* __restrict__ bih3, const float* __restrict__ bhh3,
                 const float* __restrict__ wih4, const float* __restrict__ whh4,
                 const float* __restrict__ bih4, const float* __restrict__ bhh4,
                 float* __restrict__ out)
{
    extern __shared__ char raw[];
    Smem* sm = (Smem*)raw;

    const int tid   = threadIdx.x;
    const int wid   = tid >> 5;
    const int lane  = tid & 31;
    const int bbase = blockIdx.x * 2;

    stage<32, 30, 32>(&sm->wt1[0][0][0], wih1, whh1, tid);
    stage<30, 15, 16>(&sm->wt2[0][0][0], wih2, whh2, tid);
    stage<15, 30, 32>(&sm->wt3[0][0][0], wih3, whh3, tid);
    stage<30, 16, 16>(&sm->wt4[0][0][0], wih4, whh4, tid);
    {
        float2 z2 = {0, 0};
        float2* bufs[5] = { &sm->xb[0][0][0], &sm->hb1[0][0][0], &sm->hb2[0][0][0],
                            &sm->hb3[0][0][0], &sm->hb4[0][0][0] };
#pragma unroll
        for (int b = 0; b < 5; ++b)
            for (int i = tid; i < 2 * KS * 32; i += NTHR) bufs[b][i] = z2;
    }
    __syncthreads();

    // Prelude: x steps 0..7 into xb[1] (interval 0 reads parity 1-p = 1).
    if (wid == 4) {
#pragma unroll
        for (int j = 0; j < KS; ++j) {
            size_t off = (size_t)j * 32 + lane;
            float2 xv;
            xv.x = __ldg(x + (size_t)(bbase + 0) * T_LEN * 32 + off);
            xv.y = __ldg(x + (size_t)(bbase + 1) * T_LEN * 32 + off);
            sm->xb[1][j][lane] = xv;
        }
    }
    __syncthreads();

    // SMSP = wid % 4. Lightest layer (L2) shares SMSP0 with the FC warp.
    if      (wid == 0) layer_warp<30, 15, 16, 1>(&sm->wt2[0][0][0], bih2, bhh2, sm->hb1, sm->hb2, lane);
    else if (wid == 1) layer_warp<32, 30, 32, 0>(&sm->wt1[0][0][0], bih1, bhh1, sm->xb,  sm->hb1, lane);
    else if (wid == 2) layer_warp<15, 30, 32, 2>(&sm->wt3[0][0][0], bih3, bhh3, sm->hb2, sm->hb3, lane);
    else if (wid == 3) layer_warp<30, 16, 16, 3>(&sm->wt4[0][0][0], bih4, bhh4, sm->hb3, sm->hb4, lane);
    else               fc_warp(fcw, fcb, x, out, bbase, lane, sm->hb4, sm->xb);
}

extern "C" void kernel_launch(void* const* d_in, const int* in_sizes, int n_in,
                              void* d_out, int out_size) {
    (void)in_sizes; (void)n_in; (void)out_size;
    const float* x    = (const float*)d_in[0];
    const float* fcw  = (const float*)d_in[1];
    const float* fcb  = (const float*)d_in[2];
    const float* wih1 = (const float*)d_in[3];
    const float* whh1 = (const float*)d_in[4];
    const float* bih1 = (const float*)d_in[5];
    const float* bhh1 = (const float*)d_in[6];
    const float* wih2 = (const float*)d_in[7];
    const float* whh2 = (const float*)d_in[8];
    const float* bih2 = (const float*)d_in[9];
    const float* bhh2 = (const float*)d_in[10];
    const float* wih3 = (const float*)d_in[11];
    const float* whh3 = (const float*)d_in[12];
    const float* bih3 = (const float*)d_in[13];
    const float* bhh3 = (const float*)d_in[14];
    const float* wih4 = (const float*)d_in[15];
    const float* whh4 = (const float*)d_in[16];
    const float* bih4 = (const float*)d_in[17];
    const float* bhh4 = (const float*)d_in[18];
    float* out = (float*)d_out;

    cudaFuncSetAttribute(gru_ae_k8_kernel,
                         cudaFuncAttributeMaxDynamicSharedMemorySize,
                         (int)sizeof(Smem));

    gru_ae_k8_kernel<<<NBLK, NTHR, sizeof(Smem)>>>(
        x, fcw, fcb,
        wih1, whh1, bih1, bhh1,
        wih2, whh2, bih2, bhh2,
        wih3, whh3, bih3, bhh3,
        wih4, whh4, bih4, bhh4,
        out);
}

// round 10
// speedup vs baseline: 10.6198x; 1.5285x over previous
#include <cuda_runtime.h>
#include <cstddef>

// GRU_AE fused, layer-pipelined, K=8 steps/barrier-interval, 2 batches/block,
// 256 blocks (2 blocks/SM, single wave).
// Round-10 changes vs K8 kernel:
//  * all gate dots use fma.rn.f32x2 (halves fma-pipe ops; 2 batches = 1 pair)
//  * h-side weights in REGISTERS; {w,w} packed per use via volatile mov (alu
//    pipe, dual-flows with fma pipe)
//  * x-phase accumulators pass to the serial h-phase via per-warp smem scratch
//    (keeps the h j-loop rolled -> bounded registers)
//  * layer->warp map staggered by block parity so co-resident blocks put
//    DIFFERENT layers on the same SMSP (L1 pairs with L3/L4, not with L1)

#define T_LEN 2048
#define NTHR  160
#define NBLK  256    // * 2 batches = 512
#define KS    8
#define NINT  (T_LEN / KS + 4)   // 260

#define BAR() asm volatile("bar.sync 0, %0;" :: "n"(NTHR) : "memory")
#define PACK2(d, s)      asm("mov.b64 %0, {%1, %1};" : "=l"(d) : "f"(s))
#define PACK2V(d, s)     asm volatile("mov.b64 %0, {%1, %1};" : "=l"(d) : "f"(s))
#define UNPACK2(a, b, s) asm("mov.b64 {%0, %1}, %2;" : "=f"(a), "=f"(b) : "l"(s))
#define FMA2(acc, w, v)  asm("fma.rn.f32x2 %0, %1, %2, %0;" : "+l"(acc) : "l"(w), "l"(v))

typedef unsigned long long u64;

struct Smem {
    float2 xb [2][KS][32];
    float2 hb1[2][KS][32];
    float2 hb2[2][KS][32];
    float2 hb3[2][KS][32];
    float2 hb4[2][KS][32];
    float2 gx [4][3][KS][32];   // per-layer-warp x-accum scratch (same-interval)
    float  wtx1[3][32][30];     // x-side weights, transposed [gate][col][unit]
    float  wtx2[3][30][15];
    float  wtx3[3][15][30];
    float  wtx4[3][30][16];
};

static __device__ __forceinline__ float sigm(float x) {
    return __fdividef(1.0f, 1.0f + __expf(-x));
}
static __device__ __forceinline__ float tanh_f(float x) {
    float e = __expf(2.0f * x);
    return 1.0f - __fdividef(2.0f, e + 1.0f);
}

// Stage x-side weights transposed: dst[(g*IN + c)*HID + u] = wih[(g*HID+u)*IN + c]
template <int IN, int HID>
static __device__ void stage_x(float* dst, const float* __restrict__ wih, int tid) {
    for (int i = tid; i < 3 * IN * HID; i += NTHR) {
        int u = i % HID;
        int gc = i / HID;
        int c = gc % IN;
        int g = gc / IN;
        dst[(g * IN + c) * HID + u] = wih[(g * HID + u) * IN + c];
    }
}

template <int IN, int HID, int DELAY>
static __device__ void layer_warp(
    const float* __restrict__ wtx,      // smem [3][IN][HID]
    float2 (*gx)[KS][32],               // smem scratch [3][KS][32] (this warp's)
    const float* __restrict__ whh,      // global [3H][H]
    const float* __restrict__ bih, const float* __restrict__ bhh,
    const float2 (*vb)[KS][32], float2 (*hb)[KS][32], int lane)
{
    const int hc = (lane < HID) ? lane : 0;

    // h-side weights into registers (own row of each gate).
    float wr[HID], wz[HID], wn[HID];
#pragma unroll
    for (int c = 0; c < HID; ++c) {
        wr[c] = __ldg(whh + (0 * HID + hc) * HID + c);
        wz[c] = __ldg(whh + (1 * HID + hc) * HID + c);
        wn[c] = __ldg(whh + (2 * HID + hc) * HID + c);
    }
    const float br = __ldg(bih + hc)           + __ldg(bhh + hc);
    const float bz = __ldg(bih + HID + hc)     + __ldg(bhh + HID + hc);
    const float bm = __ldg(bih + 2 * HID + hc);    // b_ih_n
    const float bn = __ldg(bhh + 2 * HID + hc);    // b_hh_n
    u64 pbr, pbz, pbm;
    PACK2(pbr, br); PACK2(pbz, bz); PACK2(pbm, bm);

    float2 hp = {0.f, 0.f};

    for (int m = 0; m < NINT; ++m) {
        const int p = m & 1;
        if (m >= DELAY && m < DELAY + T_LEN / KS) {
            // ---------- x-phase: 8 independent steps, packed FFMA2 ----------
            u64 axr[KS], axz[KS], axn[KS];
#pragma unroll
            for (int j = 0; j < KS; ++j) { axr[j] = pbr; axz[j] = pbz; axn[j] = pbm; }
#pragma unroll 4
            for (int c = 0; c < IN; ++c) {
                u64 wrp, wzp, wnp;
                float a = wtx[(0 * IN + c) * HID + hc];
                float b = wtx[(1 * IN + c) * HID + hc];
                float d = wtx[(2 * IN + c) * HID + hc];
                PACK2(wrp, a); PACK2(wzp, b); PACK2(wnp, d);
#pragma unroll
                for (int j = 0; j < KS; ++j) {
                    u64 v2 = *(const u64*)&vb[1 - p][j][c];   // broadcast LDS.64
                    FMA2(axr[j], wrp, v2);
                    FMA2(axz[j], wzp, v2);
                    FMA2(axn[j], wnp, v2);
                }
            }
#pragma unroll
            for (int j = 0; j < KS; ++j) {
                *(u64*)&gx[0][j][lane] = axr[j];
                *(u64*)&gx[1][j][lane] = axz[j];
                *(u64*)&gx[2][j][lane] = axn[j];
            }
            __syncwarp();
            // ---------- h-phase: serial over 8 steps (rolled j-loop) ----------
#pragma unroll 1
            for (int j = 0; j < KS; ++j) {
                u64 ar = *(const u64*)&gx[0][j][lane];
                u64 az = *(const u64*)&gx[1][j][lane];
                u64 an; PACK2V(an, bn);
                const float2* hv = (j == 0) ? hb[1 - p][KS - 1] : hb[p][j - 1];
#pragma unroll
                for (int c = 0; c < HID; ++c) {
                    u64 h2 = *(const u64*)&hv[c];             // broadcast LDS.64
                    u64 t;
                    PACK2V(t, wr[c]); FMA2(ar, t, h2);
                    PACK2V(t, wz[c]); FMA2(az, t, h2);
                    PACK2V(t, wn[c]); FMA2(an, t, h2);
                }
                float arx, ary, azx, azy, anx, any_, mx, my;
                UNPACK2(arx, ary, ar);
                UNPACK2(azx, azy, az);
                UNPACK2(anx, any_, an);
                {
                    u64 m2 = *(const u64*)&gx[2][j][lane];
                    UNPACK2(mx, my, m2);
                }
                float rx = sigm(arx), ry = sigm(ary);
                float zx = sigm(azx), zy = sigm(azy);
                float nx = tanh_f(fmaf(rx, anx, mx));
                float ny = tanh_f(fmaf(ry, any_, my));
                float2 hn;
                hn.x = nx + zx * (hp.x - nx);
                hn.y = ny + zy * (hp.y - ny);
                hp = hn;
                if (lane < HID) hb[p][j][lane] = hn;
                __syncwarp();            // order STS before next step's LDS
            }
        }
        BAR();                           // one barrier per 8 timesteps
    }
}

// Warp 4: FC for steps 8(m-4)+j + x loader for interval m+1.
static __device__ void fc_warp(
    const float* __restrict__ fcw, const float* __restrict__ fcb,
    const float* __restrict__ x,   float* __restrict__ out,
    int bbase, int lane,
    const float2 (*hb4)[KS][32], float2 (*xb)[KS][32])
{
    const int c10 = (lane < 10) ? lane : 0;
    float w[16];
#pragma unroll
    for (int c = 0; c < 16; ++c) w[c] = __ldg(fcw + c10 * 16 + c);
    const float bfc = __ldg(fcb + c10);

    for (int m = 0; m < NINT; ++m) {
        const int p = m & 1;
#pragma unroll
        for (int j = 0; j < KS; ++j) {
            int s = KS * (m + 1) + j;
            if (s < T_LEN) {
                size_t off = (size_t)s * 32 + lane;
                float2 xv;
                xv.x = __ldg(x + (size_t)(bbase + 0) * T_LEN * 32 + off);
                xv.y = __ldg(x + (size_t)(bbase + 1) * T_LEN * 32 + off);
                xb[p][j][lane] = xv;
            }
        }
        if (m >= 4) {
#pragma unroll
            for (int j = 0; j < KS; ++j) {
                int t = KS * (m - 4) + j;
                const float2* h4 = hb4[1 - p][j];
                float2 acc = make_float2(bfc, bfc);
#pragma unroll
                for (int c = 0; c < 16; ++c) {
                    float2 v = h4[c];
                    acc.x = fmaf(w[c], v.x, acc.x);
                    acc.y = fmaf(w[c], v.y, acc.y);
                }
                if (lane < 10) {
                    size_t base = ((size_t)bbase * 10 + lane) * T_LEN + t;
                    out[base]                      = acc.x;
                    out[base + 10 * (size_t)T_LEN] = acc.y;
                }
            }
        }
        BAR();
    }
}

__global__ void __launch_bounds__(NTHR, 2)
gru_ae_k8b_kernel(const float* __restrict__ x,
                  const float* __restrict__ fcw,  const float* __restrict__ fcb,
                  const float* __restrict__ wih1, const float* __restrict__ whh1,
                  const float* __restrict__ bih1, const float* __restrict__ bhh1,
                  const float* __restrict__ wih2, const float* __restrict__ whh2,
                  const float* __restrict__ bih2, const float* __restrict__ bhh2,
                  const float* __restrict__ wih3, const float* __restrict__ whh3,
                  const float* __restrict__ bih3, const float* __restrict__ bhh3,
                  const float* __restrict__ wih4, const float* __restrict__ whh4,
                  const float* __restrict__ bih4, const float* __restrict__ bhh4,
                  float* __restrict__ out)
{
    extern __shared__ char raw[];
    Smem* sm = (Smem*)raw;

    const int tid   = threadIdx.x;
    const int wid   = tid >> 5;
    const int lane  = tid & 31;
    const int bbase = blockIdx.x * 2;
    const bool odd  = (blockIdx.x & 1) != 0;

    stage_x<32, 30>(&sm->wtx1[0][0][0], wih1, tid);
    stage_x<30, 15>(&sm->wtx2[0][0][0], wih2, tid);
    stage_x<15, 30>(&sm->wtx3[0][0][0], wih3, tid);
    stage_x<30, 16>(&sm->wtx4[0][0][0], wih4, tid);
    {
        float2 z2 = {0, 0};
        float2* bufs[5] = { &sm->xb[0][0][0], &sm->hb1[0][0][0], &sm->hb2[0][0][0],
                            &sm->hb3[0][0][0], &sm->hb4[0][0][0] };
#pragma unroll
        for (int b = 0; b < 5; ++b)
            for (int i = tid; i < 2 * KS * 32; i += NTHR) bufs[b][i] = z2;
    }
    __syncthreads();

    // Prelude: x steps 0..7 into xb[1] (interval 0 reads parity 1-p = 1).
    if (wid == 4) {
#pragma unroll
        for (int j = 0; j < KS; ++j) {
            size_t off = (size_t)j * 32 + lane;
            float2 xv;
            xv.x = __ldg(x + (size_t)(bbase + 0) * T_LEN * 32 + off);
            xv.y = __ldg(x + (size_t)(bbase + 1) * T_LEN * 32 + off);
            sm->xb[1][j][lane] = xv;
        }
    }
    __syncthreads();

    // Parity-staggered layer->warp map (SMSP = wid%4):
    //  even block: wid0=L2 wid1=L1 wid2=L3 wid3=L4
    //  odd  block: wid0=L4 wid1=L3 wid2=L2 wid3=L1
    // => SMSP pairs across the 2 co-resident blocks: {L2,L4} {L1,L3} {L3,L2} {L4,L1}
    if (wid == 4) {
        fc_warp(fcw, fcb, x, out, bbase, lane, sm->hb4, sm->xb);
    } else if ((!odd && wid == 1) || (odd && wid == 3)) {
        layer_warp<32, 30, 0>(&sm->wtx1[0][0][0], sm->gx[0], whh1, bih1, bhh1,
                              sm->xb,  sm->hb1, lane);
    } else if ((!odd && wid == 0) || (odd && wid == 2)) {
        layer_warp<30, 15, 1>(&sm->wtx2[0][0][0], sm->gx[1], whh2, bih2, bhh2,
                              sm->hb1, sm->hb2, lane);
    } else if ((!odd && wid == 2) || (odd && wid == 1)) {
        layer_warp<15, 30, 2>(&sm->wtx3[0][0][0], sm->gx[2], whh3, bih3, bhh3,
                              sm->hb2, sm->hb3, lane);
    } else {
        layer_warp<30, 16, 3>(&sm->wtx4[0][0][0], sm->gx[3], whh4, bih4, bhh4,
                              sm->hb3, sm->hb4, lane);
    }
}

extern "C" void kernel_launch(void* const* d_in, const int* in_sizes, int n_in,
                              void* d_out, int out_size) {
    (void)in_sizes; (void)n_in; (void)out_size;
    const float* x    = (const float*)d_in[0];
    const float* fcw  = (const float*)d_in[1];
    const float* fcb  = (const float*)d_in[2];
    const float* wih1 = (const float*)d_in[3];
    const float* whh1 = (const float*)d_in[4];
    const float* bih1 = (const float*)d_in[5];
    const float* bhh1 = (const float*)d_in[6];
    const float* wih2 = (const float*)d_in[7];
    const float* whh2 = (const float*)d_in[8];
    const float* bih2 = (const float*)d_in[9];
    const float* bhh2 = (const float*)d_in[10];
    const float* wih3 = (const float*)d_in[11];
    const float* whh3 = (const float*)d_in[12];
    const float* bih3 = (const float*)d_in[13];
    const float* bhh3 = (const float*)d_in[14];
    const float* wih4 = (const float*)d_in[15];
    const float* whh4 = (const float*)d_in[16];
    const float* bih4 = (const float*)d_in[17];
    const float* bhh4 = (const float*)d_in[18];
    float* out = (float*)d_out;

    cudaFuncSetAttribute(gru_ae_k8b_kernel,
                         cudaFuncAttributeMaxDynamicSharedMemorySize,
                         (int)sizeof(Smem));

    gru_ae_k8b_kernel<<<NBLK, NTHR, sizeof(Smem)>>>(
        x, fcw, fcb,
        wih1, whh1, bih1, bhh1,
        wih2, whh2, bih2, bhh2,
        wih3, whh3, bih3, bhh3,
        wih4, whh4, bih4, bhh4,
        out);
}